// round 15
// baseline (speedup 1.0000x reference)
#include <cuda_runtime.h>
#include <cuda_bf16.h>
#include <math.h>
#include <stdint.h>

#define BSZ 8
#define LSEQ 4096
#define DM 512
#define NS 64
#define NROWS (BSZ*LSEQ)

// scratch (allocations forbidden -> device globals)
// all pre-swizzled SW128 bf16 layouts: element (row, col2B) at row*128 + SW-in-row
__device__ __align__(16) unsigned char g_Buh[NROWS*128];   // Bu hi split
__device__ __align__(16) unsigned char g_Bul[NROWS*128];   // Bu lo split
__device__ __align__(16) unsigned char g_Sth[NROWS*128];   // states hi
__device__ __align__(16) unsigned char g_Stl[NROWS*128];   // states lo
__device__ __align__(16) unsigned char g_Bh[65536], g_Bl[65536];   // B [8 kc][64 n][64 k]
__device__ __align__(16) unsigned char g_Ch[65536], g_Cl[65536];   // C [512 d][64 n]
__device__ __align__(16) unsigned char g_Mh[24576], g_Ml[24576];   // A,A2,A4 [p][64 n][64 m]

// ===================== helpers (sm_80-era PTX only) =====================
__device__ __forceinline__ uint32_t smem_u32(const void* p) {
    uint32_t a;
    asm("{ .reg .u64 t; cvta.to.shared.u64 t, %1; cvt.u32.u64 %0, t; }" : "=r"(a) : "l"(p));
    return a;
}
#define SW(o) ((uint32_t)(o) ^ ((((uint32_t)(o)) >> 3) & 0x70))

__device__ __forceinline__ void ldsm4(uint32_t r[4], uint32_t addr) {
    asm volatile("ldmatrix.sync.aligned.m8n8.x4.shared.b16 {%0,%1,%2,%3}, [%4];"
        : "=r"(r[0]), "=r"(r[1]), "=r"(r[2]), "=r"(r[3]) : "r"(addr));
}
__device__ __forceinline__ void mma_bf16(float c[4], const uint32_t a[4],
                                         uint32_t b0, uint32_t b1) {
    asm volatile("mma.sync.aligned.m16n8k16.row.col.f32.bf16.bf16.f32 "
        "{%0,%1,%2,%3}, {%4,%5,%6,%7}, {%8,%9}, {%0,%1,%2,%3};"
        : "+f"(c[0]), "+f"(c[1]), "+f"(c[2]), "+f"(c[3])
        : "r"(a[0]), "r"(a[1]), "r"(a[2]), "r"(a[3]), "r"(b0), "r"(b1));
}
__device__ __forceinline__ void split_pair(float a, float b, uint32_t& h, uint32_t& l) {
    __nv_bfloat16 ha = __float2bfloat16_rn(a), hb = __float2bfloat16_rn(b);
    float ra = a - __bfloat162float(ha);
    float rb = b - __bfloat162float(hb);
    __nv_bfloat16 la = __float2bfloat16_rn(ra), lb = __float2bfloat16_rn(rb);
    h = (uint32_t)__bfloat16_as_ushort(ha) | ((uint32_t)__bfloat16_as_ushort(hb) << 16);
    l = (uint32_t)__bfloat16_as_ushort(la) | ((uint32_t)__bfloat16_as_ushort(lb) << 16);
}
__device__ __forceinline__ float gelu_exact(float v) {
    return 0.5f * v * (1.0f + erff(v * 0.70710678118654752440f));
}
// Taylor erf for |z|<0.5 (error < 5e-7)
__device__ __forceinline__ float gelu_poly(float v) {
    float z = v * 0.70710678f;
    float z2 = z * z;
    float p = fmaf(z2, fmaf(z2, fmaf(z2, fmaf(z2, 5.2239776e-3f, -2.6866170e-2f),
                1.1283792e-1f), -3.7612638e-1f), 1.1283792f);
    return 0.5f * v * fmaf(z, p, 1.0f);
}
// cp.async (sm_80 PTX, assembles for compute_103)
__device__ __forceinline__ void cpa16(uint32_t dst, const void* src) {
    asm volatile("cp.async.cg.shared.global [%0], [%1], 16;" :: "r"(dst), "l"(src));
}
__device__ __forceinline__ void cpa16z(uint32_t dst, const void* src, bool valid) {
    int sz = valid ? 16 : 0;
    asm volatile("cp.async.cg.shared.global [%0], [%1], 16, %2;"
                 :: "r"(dst), "l"(src), "r"(sz));
}
#define CPA_COMMIT() asm volatile("cp.async.commit_group;" ::: "memory")
#define CPA_WAIT(n)  asm volatile("cp.async.wait_group %0;" :: "n"(n) : "memory")

// ---------------------------------------------------------------------------
// init: blocks 0..127 split B/C (512 thr); block 128 computes A2/A4 + splits
// ---------------------------------------------------------------------------
__global__ __launch_bounds__(512) void init_kernel(const float* __restrict__ A,
                                                   const float* __restrict__ B,
                                                   const float* __restrict__ C) {
    __shared__ float As[NS*NS], A2s[NS*NS], A4s[NS*NS];
    int tid = threadIdx.x;
    if (blockIdx.x < 128) {
        int i = blockIdx.x*512 + tid;
        if (i < 32768) {
            int n = i >> 9, k = i & 511;
            float v = B[i];
            __nv_bfloat16 h = __float2bfloat16_rn(v);
            __nv_bfloat16 l = __float2bfloat16_rn(v - __bfloat162float(h));
            uint32_t ofs = (uint32_t)(k >> 6)*8192u + SW((uint32_t)(n*128 + (k & 63)*2));
            *(__nv_bfloat16*)(g_Bh + ofs) = h;
            *(__nv_bfloat16*)(g_Bl + ofs) = l;
        } else {
            int j = i - 32768;
            int d = j >> 6, k = j & 63;
            float v = C[j];
            __nv_bfloat16 h = __float2bfloat16_rn(v);
            __nv_bfloat16 l = __float2bfloat16_rn(v - __bfloat162float(h));
            uint32_t ofs = SW((uint32_t)(d*128 + k*2));
            *(__nv_bfloat16*)(g_Ch + ofs) = h;
            *(__nv_bfloat16*)(g_Cl + ofs) = l;
        }
        return;
    }
    // prep path (single block, 512 threads)
    for (int i = tid; i < NS*NS; i += 512) As[i] = A[i];
    __syncthreads();
    for (int e = tid; e < NS*NS; e += 512) {
        int n = e >> 6, m = e & 63;
        float acc = 0.f;
        #pragma unroll 8
        for (int k = 0; k < NS; k++) acc += As[n*NS + k] * As[k*NS + m];
        A2s[e] = acc;
    }
    __syncthreads();
    for (int e = tid; e < NS*NS; e += 512) {
        int n = e >> 6, m = e & 63;
        float acc = 0.f;
        #pragma unroll 8
        for (int k = 0; k < NS; k++) acc += A2s[n*NS + k] * A2s[k*NS + m];
        A4s[e] = acc;
    }
    __syncthreads();
    for (int e = tid; e < NS*NS; e += 512) {
        int n = e >> 6, m = e & 63;
        float vs[3] = {As[e], A2s[e], A4s[e]};
        uint32_t ofs = SW((uint32_t)(n*128 + m*2));
        #pragma unroll
        for (int p = 0; p < 3; p++) {
            __nv_bfloat16 h = __float2bfloat16_rn(vs[p]);
            __nv_bfloat16 l = __float2bfloat16_rn(vs[p] - __bfloat162float(h));
            *(__nv_bfloat16*)(g_Mh + p*8192 + ofs) = h;
            *(__nv_bfloat16*)(g_Ml + p*8192 + ofs) = l;
        }
    }
}

// ---------------------------------------------------------------------------
// Stage 1 (v5 — proven): Bu = x @ B^T. 64-row tiles, grid 512, 256 threads,
// 3 CTA/SM. x staged RAW via cp.async; split from smem; B double-buffered.
// ---------------------------------------------------------------------------
#define B1_RAW   0                           // 16 KB raw f32 x chunk
#define B1_XHI   16384                       // 8 KB split hi
#define B1_XLO   24576                       // 8 KB split lo
#define B1_BHI(b) (32768 + (b)*16384)        // B chunk hi
#define B1_BLO(b) (40960 + (b)*16384)        // B chunk lo
#define B1_SMEM  65536

__global__ __launch_bounds__(256, 3) void bu_mma(const float* __restrict__ x) {
    extern __shared__ char sm[];
    uint32_t smb = smem_u32(sm);
    int tid = threadIdx.x, wid = tid >> 5, lane = tid & 31;
    int row0 = blockIdx.x * 64;
    int mrow = (wid >> 2) * 32, ncol = (wid & 3) * 16;

    float acc[2][2][4];
    #pragma unroll
    for (int mf = 0; mf < 2; mf++)
        #pragma unroll
        for (int nf = 0; nf < 2; nf++)
            #pragma unroll
            for (int cc = 0; cc < 4; cc++) acc[mf][nf][cc] = 0.f;

    int a_r = lane & 15, a_k = (lane >> 4) << 4;
    int b_m = lane >> 3;
    int b_n = ((b_m >> 1) << 3) + (lane & 7);
    int b_k = (b_m & 1) << 4;

    // prologue: request raw x(0) + B(0)
    #pragma unroll
    for (int it = 0; it < 4; it++) {
        int f = it*256 + tid;                 // 0..1023 (16B lines)
        int r = f >> 4, c4 = (f & 15) << 2;
        cpa16(smb + B1_RAW + f*16, &x[(size_t)(row0 + r)*DM + c4]);
    }
    #pragma unroll
    for (int it = 0; it < 4; it++) {
        int f = it*256 + tid;
        int buf = f >> 9, idx = f & 511;
        cpa16(smb + (buf ? B1_BLO(0) : B1_BHI(0)) + idx*16,
              (buf ? g_Bl : g_Bh) + idx*16);
    }
    CPA_COMMIT();

    #pragma unroll
    for (int kc = 0; kc < 8; kc++) {
        int cur = kc & 1, nxt = cur ^ 1;
        CPA_WAIT(0);       // raw(kc) + B(kc) landed
        __syncthreads();   // + all MMA(kc-1) reads (incl. B(nxt)) complete
        // split raw f32 -> XHI/XLO bf16
        #pragma unroll
        for (int it = 0; it < 4; it++) {
            int f = it*256 + tid;
            int r = f >> 4, c4 = (f & 15) << 2;
            float4 v = *(const float4*)(sm + B1_RAW + f*16);
            uint32_t h0, l0, h1, l1;
            split_pair(v.x, v.y, h0, l0);
            split_pair(v.z, v.w, h1, l1);
            uint32_t off = SW((uint32_t)(r*128 + c4*2));
            *(uint2*)(sm + B1_XHI + off) = make_uint2(h0, h1);
            *(uint2*)(sm + B1_XLO + off) = make_uint2(l0, l1);
        }
        __syncthreads();   // split visible; RAW free for rewrite
        if (kc < 7) {
            // prefetch chunk kc+1 (overlaps MMA(kc))
            #pragma unroll
            for (int it = 0; it < 4; it++) {
                int f = it*256 + tid;
                int r = f >> 4, c4 = (f & 15) << 2;
                cpa16(smb + B1_RAW + f*16,
                      &x[(size_t)(row0 + r)*DM + (kc + 1)*64 + c4]);
            }
            #pragma unroll
            for (int it = 0; it < 4; it++) {
                int f = it*256 + tid;
                int buf = f >> 9, idx = f & 511;
                cpa16(smb + (buf ? B1_BLO(nxt) : B1_BHI(nxt)) + idx*16,
                      (buf ? g_Bl : g_Bh) + (kc + 1)*8192 + idx*16);
            }
            CPA_COMMIT();
        }
        #pragma unroll
        for (int ks = 0; ks < 4; ks++) {
            uint32_t ah[2][4], al[2][4];
            #pragma unroll
            for (int mf = 0; mf < 2; mf++) {
                uint32_t off = SW((uint32_t)((mrow + mf*16 + a_r)*128 + ks*32 + a_k));
                ldsm4(ah[mf], smb + B1_XHI + off);
                ldsm4(al[mf], smb + B1_XLO + off);
            }
            uint32_t boff = SW((uint32_t)((ncol + b_n)*128 + ks*32 + b_k));
            uint32_t bh[4], bl[4];
            ldsm4(bh, smb + B1_BHI(cur) + boff);
            ldsm4(bl, smb + B1_BLO(cur) + boff);
            #pragma unroll
            for (int mf = 0; mf < 2; mf++) {
                mma_bf16(acc[mf][0], ah[mf], bh[0], bh[1]);
                mma_bf16(acc[mf][0], ah[mf], bl[0], bl[1]);
                mma_bf16(acc[mf][0], al[mf], bh[0], bh[1]);
                mma_bf16(acc[mf][1], ah[mf], bh[2], bh[3]);
                mma_bf16(acc[mf][1], ah[mf], bl[2], bl[3]);
                mma_bf16(acc[mf][1], al[mf], bh[2], bh[3]);
            }
        }
    }
    // spill pre-split + swizzled
    int rg = lane >> 2, q = lane & 3;
    #pragma unroll
    for (int mf = 0; mf < 2; mf++)
        #pragma unroll
        for (int nf = 0; nf < 2; nf++) {
            uint32_t r = (uint32_t)(row0 + mrow + mf*16 + rg);
            uint32_t colb = (uint32_t)(ncol + nf*8 + q*2) * 2;
            uint32_t h, l;
            split_pair(acc[mf][nf][0], acc[mf][nf][1], h, l);
            uint32_t ofs = SW(r*128 + colb);
            *(uint32_t*)(g_Buh + ofs) = h;
            *(uint32_t*)(g_Bul + ofs) = l;
            split_pair(acc[mf][nf][2], acc[mf][nf][3], h, l);
            ofs = SW((r + 8)*128 + colb);
            *(uint32_t*)(g_Buh + ofs) = h;
            *(uint32_t*)(g_Bul + ofs) = l;
        }
}

// ---------------------------------------------------------------------------
// Stage 2: three chained shift-GEMM passes (delta 1,2,4), acc in registers.
// (unchanged — proven ~19us)
// ---------------------------------------------------------------------------
#define P_AHI 0
#define P_ALO 19456
#define P_MHI 38912
#define P_MLO 63488
#define P_SMEM 88064

__global__ __launch_bounds__(288, 2) void pass_mma() {
    extern __shared__ char sm[];
    uint32_t smb = smem_u32(sm);
    int tid = threadIdx.x, wid = tid >> 5, lane = tid & 31;
    int b = blockIdx.x >> 5, c = blockIdx.x & 31;
    int t0 = c * 128;
    size_t gbase = (size_t)b * LSEQ;

    for (int f = tid; f < 256; f += 288) {
        int buf = f >> 7, g = f & 127, pr = g >> 3, j = g & 7;
        int row = (pr < 8) ? pr : pr + 136;
        *(uint4*)(sm + (buf ? P_ALO : P_AHI) + row*128 + j*16) = make_uint4(0,0,0,0);
    }
    for (int f = tid; f < 2176; f += 288) {
        int buf = (f >= 1088) ? 1 : 0;
        int g = buf ? f - 1088 : f;
        int r = g >> 3, j = g & 7;
        int t = t0 - 8 + r;
        size_t ts = (t < 0) ? 0 : (size_t)t;
        cpa16z(smb + (buf ? P_ALO : P_AHI) + (8 + r)*128 + j*16,
               (buf ? g_Bul : g_Buh) + (gbase + ts)*128 + j*16, t >= 0);
    }
    for (int f = tid; f < 3072; f += 288) {
        int buf = (f >= 1536) ? 1 : 0;
        int idx = buf ? f - 1536 : f;
        cpa16(smb + (buf ? P_MLO : P_MHI) + idx*16, (buf ? g_Ml : g_Mh) + idx*16);
    }
    CPA_COMMIT();
    CPA_WAIT(0);
    __syncthreads();

    int i0 = 8 + wid*16;
    int rg = lane >> 2, q = lane & 3;
    int r0 = i0 + rg, r1 = r0 + 8;
    int a_r = lane & 15, a_k = (lane >> 4) << 4;
    int b_m = lane >> 3;
    int b_n = ((b_m >> 1) << 3) + (lane & 7);
    int b_k = (b_m & 1) << 4;

    float acc[8][4];
    #pragma unroll
    for (int nf = 0; nf < 8; nf++) {
        uint32_t colb = (uint32_t)(nf*8 + q*2) * 2;
        uint32_t o0 = SW((uint32_t)(r0*128) + colb);
        uint32_t o1 = SW((uint32_t)(r1*128) + colb);
        float2 h0 = __bfloat1622float2(*(__nv_bfloat162*)(sm + P_AHI + o0));
        float2 l0 = __bfloat1622float2(*(__nv_bfloat162*)(sm + P_ALO + o0));
        float2 h1 = __bfloat1622float2(*(__nv_bfloat162*)(sm + P_AHI + o1));
        float2 l1 = __bfloat1622float2(*(__nv_bfloat162*)(sm + P_ALO + o1));
        acc[nf][0] = h0.x + l0.x; acc[nf][1] = h0.y + l0.y;
        acc[nf][2] = h1.x + l1.x; acc[nf][3] = h1.y + l1.y;
    }

    #pragma unroll
    for (int p = 0; p < 3; p++) {
        const int delta = 1 << p;
        #pragma unroll
        for (int ks = 0; ks < 4; ks++) {
            uint32_t ah[4], al[4];
            uint32_t aoff = SW((uint32_t)((i0 - delta + a_r)*128 + ks*32 + a_k));
            ldsm4(ah, smb + P_AHI + aoff);
            ldsm4(al, smb + P_ALO + aoff);
            #pragma unroll
            for (int nfp = 0; nfp < 4; nfp++) {
                uint32_t boff = p*8192 + SW((uint32_t)((nfp*16 + b_n)*128 + ks*32 + b_k));
                uint32_t bh[4], bl[4];
                ldsm4(bh, smb + P_MHI + boff);
                ldsm4(bl, smb + P_MLO + boff);
                mma_bf16(acc[2*nfp],   ah, bh[0], bh[1]);
                mma_bf16(acc[2*nfp],   ah, bl[0], bl[1]);
                mma_bf16(acc[2*nfp],   al, bh[0], bh[1]);
                mma_bf16(acc[2*nfp+1], ah, bh[2], bh[3]);
                mma_bf16(acc[2*nfp+1], ah, bl[2], bl[3]);
                mma_bf16(acc[2*nfp+1], al, bh[2], bh[3]);
            }
        }
        if (p < 2) {
            __syncthreads();
            #pragma unroll
            for (int nf = 0; nf < 8; nf++) {
                uint32_t colb = (uint32_t)(nf*8 + q*2) * 2;
                uint32_t h, l;
                split_pair(acc[nf][0], acc[nf][1], h, l);
                uint32_t off = SW((uint32_t)(r0*128) + colb);
                *(uint32_t*)(sm + P_AHI + off) = h;
                *(uint32_t*)(sm + P_ALO + off) = l;
                split_pair(acc[nf][2], acc[nf][3], h, l);
                off = SW((uint32_t)(r1*128) + colb);
                *(uint32_t*)(sm + P_AHI + off) = h;
                *(uint32_t*)(sm + P_ALO + off) = l;
            }
            __syncthreads();
        }
    }
    if (r0 >= 16 && r0 < 144) {
        uint32_t R = (uint32_t)(gbase + t0 + r0 - 16);
        #pragma unroll
        for (int nf = 0; nf < 8; nf++) {
            uint32_t colb = (uint32_t)(nf*8 + q*2) * 2;
            uint32_t h, l;
            split_pair(acc[nf][0], acc[nf][1], h, l);
            uint32_t ofs = SW(R*128 + colb);
            *(uint32_t*)(g_Sth + ofs) = h;
            *(uint32_t*)(g_Stl + ofs) = l;
        }
    }
    if (r1 >= 16 && r1 < 144) {
        uint32_t R = (uint32_t)(gbase + t0 + r1 - 16);
        #pragma unroll
        for (int nf = 0; nf < 8; nf++) {
            uint32_t colb = (uint32_t)(nf*8 + q*2) * 2;
            uint32_t h, l;
            split_pair(acc[nf][2], acc[nf][3], h, l);
            uint32_t ofs = SW(R*128 + colb);
            *(uint32_t*)(g_Sth + ofs) = h;
            *(uint32_t*)(g_Stl + ofs) = l;
        }
    }
}

// ---------------------------------------------------------------------------
// Stage 3 (persistent, v2): grid=128, 1024 threads, warp grid 4M x 8N
// (16 rows x 64 cols per warp, acc 32 regs) -> 32 warps/SM at the same full
// RF. C staged ONCE; 4 row-tiles of 64 rows; S double-buffered.
// GELU poly + LayerNorm(512).
// ---------------------------------------------------------------------------
#define O_CHI 0
#define O_CLO 65536
#define O_SHI(b) (131072 + (b)*8192)
#define O_SLO(b) (147456 + (b)*8192)
#define O_GM   163840
#define O_BT   165888
#define O_PART 167936
#define O_SMEM 172032
#define O_GRID 128
#define O_ITERS (NROWS/64/O_GRID)

__global__ __launch_bounds__(1024, 1) void out_mma(const float* __restrict__ gamma,
                                                   const float* __restrict__ beta,
                                                   float* __restrict__ out) {
    extern __shared__ char sm[];
    uint32_t smb = smem_u32(sm);
    int tid = threadIdx.x, wid = tid >> 5, lane = tid & 31;
    int mg = wid >> 3, colw = wid & 7;   // 4 row-groups x 8 col-groups

    #pragma unroll
    for (int it = 0; it < 8; it++) {
        int f = it*1024 + tid;
        int buf = f >> 12, g = f & 4095;
        cpa16(smb + (buf ? O_CLO : O_CHI) + g*16, (buf ? g_Cl : g_Ch) + g*16);
    }
    {
        size_t row0 = (size_t)blockIdx.x * 64;
        int f = tid;                      // 1024 lines = 2 bufs x 512
        int buf = f >> 9, g = f & 511, r = g >> 3, j = g & 7;
        cpa16(smb + (buf ? O_SLO(0) : O_SHI(0)) + r*128 + j*16,
              (buf ? g_Stl : g_Sth) + (row0 + r)*128 + j*16);
    }
    CPA_COMMIT();
    if (tid < 512) {
        ((float*)(sm + O_GM))[tid] = gamma[tid];
        ((float*)(sm + O_BT))[tid] = beta[tid];
    }

    int a_r = lane & 15, a_k = (lane >> 4) << 4;
    int b_m = lane >> 3;
    int b_n = ((b_m >> 1) << 3) + (lane & 7);
    int b_k = (b_m & 1) << 4;
    int rg = lane >> 2, q = lane & 3;
    const float* gm = (const float*)(sm + O_GM);
    const float* bt = (const float*)(sm + O_BT);
    float2* part = (float2*)(sm + O_PART);   // [64 rows][8 colw]

    for (int it = 0; it < O_ITERS; it++) {
        int cur = it & 1;
        int tile = blockIdx.x + it*O_GRID;
        int row0 = tile * 64;

        CPA_WAIT(0);
        __syncthreads();

        if (it < O_ITERS - 1) {
            size_t nrow0 = (size_t)(blockIdx.x + (it + 1)*O_GRID) * 64;
            int f = tid;
            int buf = f >> 9, g = f & 511, r = g >> 3, j = g & 7;
            cpa16(smb + (buf ? O_SLO(cur^1) : O_SHI(cur^1)) + r*128 + j*16,
                  (buf ? g_Stl : g_Sth) + (nrow0 + r)*128 + j*16);
            CPA_COMMIT();
        }

        float acc[8][4];
        #pragma unroll
        for (int nf = 0; nf < 8; nf++)
            #pragma unroll
            for (int cc = 0; cc < 4; cc++) acc[nf][cc] = 0.f;

        #pragma unroll
        for (int ks = 0; ks < 4; ks++) {
            uint32_t ah[4], al[4];
            uint32_t aoff = SW((uint32_t)((mg*16 + a_r)*128 + ks*32 + a_k));
            ldsm4(ah, smb + O_SHI(cur) + aoff);
            ldsm4(al, smb + O_SLO(cur) + aoff);
            #pragma unroll
            for (int nfp = 0; nfp < 4; nfp++) {
                uint32_t boff = SW((uint32_t)((colw*64 + nfp*16 + b_n)*128 + ks*32 + b_k));
                uint32_t bh[4], bl[4];
                ldsm4(bh, smb + O_CHI + boff);
                ldsm4(bl, smb + O_CLO + boff);
                mma_bf16(acc[2*nfp],   ah, bh[0], bh[1]);
                mma_bf16(acc[2*nfp],   ah, bl[0], bl[1]);
                mma_bf16(acc[2*nfp],   al, bh[0], bh[1]);
                mma_bf16(acc[2*nfp+1], ah, bh[2], bh[3]);
                mma_bf16(acc[2*nfp+1], ah, bl[2], bl[3]);
                mma_bf16(acc[2*nfp+1], al, bh[2], bh[3]);
            }
        }
        // ---- epilogue: GELU (warp-uniform poly/exact) + LayerNorm ----
        float am = 0.f;
        #pragma unroll
        for (int nf = 0; nf < 8; nf++)
            #pragma unroll
            for (int cc = 0; cc < 4; cc++) am = fmaxf(am, fabsf(acc[nf][cc]));
        if (__any_sync(0xffffffffu, am > 0.70f)) {
            #pragma unroll
            for (int nf = 0; nf < 8; nf++)
                #pragma unroll
                for (int cc = 0; cc < 4; cc++) acc[nf][cc] = gelu_exact(acc[nf][cc]);
        } else {
            #pragma unroll
            for (int nf = 0; nf < 8; nf++)
                #pragma unroll
                for (int cc = 0; cc < 4; cc++) acc[nf][cc] = gelu_poly(acc[nf][cc]);
        }
        float s0 = 0.f, q0 = 0.f, s1 = 0.f, q1 = 0.f;
        #pragma unroll
        for (int nf = 0; nf < 8; nf++) {
            s0 += acc[nf][0] + acc[nf][1];
            q0 += acc[nf][0]*acc[nf][0] + acc[nf][1]*acc[nf][1];
            s1 += acc[nf][2] + acc[nf][3];
            q1 += acc[nf][2]*acc[nf][2] + acc[nf][3]*acc[nf][3];
        }
        #pragma unroll
        for (int off = 1; off <= 2; off <<= 1) {
            s0 += __shfl_xor_sync(0xffffffffu, s0, off);
            q0 += __shfl_xor_sync(0xffffffffu, q0, off);
            s1 += __shfl_xor_sync(0xffffffffu, s1, off);
            q1 += __shfl_xor_sync(0xffffffffu, q1, off);
        }
        int lr0 = mg*16 + rg, lr1 = lr0 + 8;
        if (q == 0) {
            part[lr0*8 + colw] = make_float2(s0, q0);
            part[lr1*8 + colw] = make_float2(s1, q1);
        }
        __syncthreads();
        float ts0 = 0.f, tq0 = 0.f, ts1 = 0.f, tq1 = 0.f;
        #pragma unroll
        for (int cw = 0; cw < 8; cw++) {
            float2 v0 = part[lr0*8 + cw]; ts0 += v0.x; tq0 += v0.y;
            float2 v1 = part[lr1*8 + cw]; ts1 += v1.x; tq1 += v1.y;
        }
        float mean0 = ts0 * (1.0f/512.0f);
        float rstd0 = rsqrtf(tq0 * (1.0f/512.0f) - mean0*mean0 + 1e-5f);
        float mean1 = ts1 * (1.0f/512.0f);
        float rstd1 = rsqrtf(tq1 * (1.0f/512.0f) - mean1*mean1 + 1e-5f);

        #pragma unroll
        for (int nf = 0; nf < 8; nf++) {
            int nfp = nf >> 1, h = nf & 1;
            int col = colw*64 + nfp*16 + h*8 + q*2;
            size_t r0g = (size_t)(row0 + lr0);
            float2 o0 = make_float2(
                (acc[nf][0] - mean0)*rstd0*gm[col]   + bt[col],
                (acc[nf][1] - mean0)*rstd0*gm[col+1] + bt[col+1]);
            float2 o1 = make_float2(
                (acc[nf][2] - mean1)*rstd1*gm[col]   + bt[col],
                (acc[nf][3] - mean1)*rstd1*gm[col+1] + bt[col+1]);
            *(float2*)&out[r0g*DM + col] = o0;
            *(float2*)&out[(r0g + 8)*DM + col] = o1;
        }
    }
}

// ---------------------------------------------------------------------------
extern "C" void kernel_launch(void* const* d_in, const int* in_sizes, int n_in,
                              void* d_out, int out_size) {
    const float* x     = (const float*)d_in[0];
    const float* A     = (const float*)d_in[1];
    const float* B     = (const float*)d_in[2];
    const float* C     = (const float*)d_in[3];
    const float* gamma = (const float*)d_in[4];
    const float* beta  = (const float*)d_in[5];
    float* out = (float*)d_out;

    cudaFuncSetAttribute(bu_mma,   cudaFuncAttributeMaxDynamicSharedMemorySize, B1_SMEM);
    cudaFuncSetAttribute(pass_mma, cudaFuncAttributeMaxDynamicSharedMemorySize, P_SMEM);
    cudaFuncSetAttribute(out_mma,  cudaFuncAttributeMaxDynamicSharedMemorySize, O_SMEM);

    init_kernel<<<129, 512>>>(A, B, C);
    bu_mma<<<NROWS/64, 256, B1_SMEM>>>(x);
    pass_mma<<<BSZ * (LSEQ/128), 288, P_SMEM>>>();
    out_mma<<<O_GRID, 1024, O_SMEM>>>(gamma, beta, out);
}

// round 16
// speedup vs baseline: 1.0379x; 1.0379x over previous
#include <cuda_runtime.h>
#include <cuda_bf16.h>
#include <math.h>
#include <stdint.h>

#define BSZ 8
#define LSEQ 4096
#define DM 512
#define NS 64
#define NROWS (BSZ*LSEQ)

// scratch (allocations forbidden -> device globals)
// all pre-swizzled SW128 bf16 layouts: element (row, col2B) at row*128 + SW-in-row
__device__ __align__(16) unsigned char g_Buh[NROWS*128];   // Bu hi split
__device__ __align__(16) unsigned char g_Bul[NROWS*128];   // Bu lo split
__device__ __align__(16) unsigned char g_Sth[NROWS*128];   // states hi
__device__ __align__(16) unsigned char g_Stl[NROWS*128];   // states lo
__device__ __align__(16) unsigned char g_Bh[65536], g_Bl[65536];   // B [8 kc][64 n][64 k]
__device__ __align__(16) unsigned char g_Ch[65536], g_Cl[65536];   // C [512 d][64 n]
__device__ __align__(16) unsigned char g_Mh[24576], g_Ml[24576];   // A,A2,A4 [p][64 n][64 m]

// ===================== helpers (sm_80-era PTX only) =====================
__device__ __forceinline__ uint32_t smem_u32(const void* p) {
    uint32_t a;
    asm("{ .reg .u64 t; cvta.to.shared.u64 t, %1; cvt.u32.u64 %0, t; }" : "=r"(a) : "l"(p));
    return a;
}
#define SW(o) ((uint32_t)(o) ^ ((((uint32_t)(o)) >> 3) & 0x70))

__device__ __forceinline__ void ldsm4(uint32_t r[4], uint32_t addr) {
    asm volatile("ldmatrix.sync.aligned.m8n8.x4.shared.b16 {%0,%1,%2,%3}, [%4];"
        : "=r"(r[0]), "=r"(r[1]), "=r"(r[2]), "=r"(r[3]) : "r"(addr));
}
__device__ __forceinline__ void mma_bf16(float c[4], const uint32_t a[4],
                                         uint32_t b0, uint32_t b1) {
    asm volatile("mma.sync.aligned.m16n8k16.row.col.f32.bf16.bf16.f32 "
        "{%0,%1,%2,%3}, {%4,%5,%6,%7}, {%8,%9}, {%0,%1,%2,%3};"
        : "+f"(c[0]), "+f"(c[1]), "+f"(c[2]), "+f"(c[3])
        : "r"(a[0]), "r"(a[1]), "r"(a[2]), "r"(a[3]), "r"(b0), "r"(b1));
}
__device__ __forceinline__ void split_pair(float a, float b, uint32_t& h, uint32_t& l) {
    __nv_bfloat16 ha = __float2bfloat16_rn(a), hb = __float2bfloat16_rn(b);
    float ra = a - __bfloat162float(ha);
    float rb = b - __bfloat162float(hb);
    __nv_bfloat16 la = __float2bfloat16_rn(ra), lb = __float2bfloat16_rn(rb);
    h = (uint32_t)__bfloat16_as_ushort(ha) | ((uint32_t)__bfloat16_as_ushort(hb) << 16);
    l = (uint32_t)__bfloat16_as_ushort(la) | ((uint32_t)__bfloat16_as_ushort(lb) << 16);
}
__device__ __forceinline__ float gelu_exact(float v) {
    return 0.5f * v * (1.0f + erff(v * 0.70710678118654752440f));
}
// Taylor erf for |z|<0.5 (error < 5e-7)
__device__ __forceinline__ float gelu_poly(float v) {
    float z = v * 0.70710678f;
    float z2 = z * z;
    float p = fmaf(z2, fmaf(z2, fmaf(z2, fmaf(z2, 5.2239776e-3f, -2.6866170e-2f),
                1.1283792e-1f), -3.7612638e-1f), 1.1283792f);
    return 0.5f * v * fmaf(z, p, 1.0f);
}
// cp.async (sm_80 PTX, assembles for compute_103)
__device__ __forceinline__ void cpa16(uint32_t dst, const void* src) {
    asm volatile("cp.async.cg.shared.global [%0], [%1], 16;" :: "r"(dst), "l"(src));
}
__device__ __forceinline__ void cpa16z(uint32_t dst, const void* src, bool valid) {
    int sz = valid ? 16 : 0;
    asm volatile("cp.async.cg.shared.global [%0], [%1], 16, %2;"
                 :: "r"(dst), "l"(src), "r"(sz));
}
#define CPA_COMMIT() asm volatile("cp.async.commit_group;" ::: "memory")
#define CPA_WAIT(n)  asm volatile("cp.async.wait_group %0;" :: "n"(n) : "memory")

// ---------------------------------------------------------------------------
// init: blocks 0..127 split B/C (512 thr); block 128 computes A2/A4 + splits
// ---------------------------------------------------------------------------
__global__ __launch_bounds__(512) void init_kernel(const float* __restrict__ A,
                                                   const float* __restrict__ B,
                                                   const float* __restrict__ C) {
    __shared__ float As[NS*NS], A2s[NS*NS], A4s[NS*NS];
    int tid = threadIdx.x;
    if (blockIdx.x < 128) {
        int i = blockIdx.x*512 + tid;
        if (i < 32768) {
            int n = i >> 9, k = i & 511;
            float v = B[i];
            __nv_bfloat16 h = __float2bfloat16_rn(v);
            __nv_bfloat16 l = __float2bfloat16_rn(v - __bfloat162float(h));
            uint32_t ofs = (uint32_t)(k >> 6)*8192u + SW((uint32_t)(n*128 + (k & 63)*2));
            *(__nv_bfloat16*)(g_Bh + ofs) = h;
            *(__nv_bfloat16*)(g_Bl + ofs) = l;
        } else {
            int j = i - 32768;
            int d = j >> 6, k = j & 63;
            float v = C[j];
            __nv_bfloat16 h = __float2bfloat16_rn(v);
            __nv_bfloat16 l = __float2bfloat16_rn(v - __bfloat162float(h));
            uint32_t ofs = SW((uint32_t)(d*128 + k*2));
            *(__nv_bfloat16*)(g_Ch + ofs) = h;
            *(__nv_bfloat16*)(g_Cl + ofs) = l;
        }
        return;
    }
    // prep path (single block, 512 threads)
    for (int i = tid; i < NS*NS; i += 512) As[i] = A[i];
    __syncthreads();
    for (int e = tid; e < NS*NS; e += 512) {
        int n = e >> 6, m = e & 63;
        float acc = 0.f;
        #pragma unroll 8
        for (int k = 0; k < NS; k++) acc += As[n*NS + k] * As[k*NS + m];
        A2s[e] = acc;
    }
    __syncthreads();
    for (int e = tid; e < NS*NS; e += 512) {
        int n = e >> 6, m = e & 63;
        float acc = 0.f;
        #pragma unroll 8
        for (int k = 0; k < NS; k++) acc += A2s[n*NS + k] * A2s[k*NS + m];
        A4s[e] = acc;
    }
    __syncthreads();
    for (int e = tid; e < NS*NS; e += 512) {
        int n = e >> 6, m = e & 63;
        float vs[3] = {As[e], A2s[e], A4s[e]};
        uint32_t ofs = SW((uint32_t)(n*128 + m*2));
        #pragma unroll
        for (int p = 0; p < 3; p++) {
            __nv_bfloat16 h = __float2bfloat16_rn(vs[p]);
            __nv_bfloat16 l = __float2bfloat16_rn(vs[p] - __bfloat162float(h));
            *(__nv_bfloat16*)(g_Mh + p*8192 + ofs) = h;
            *(__nv_bfloat16*)(g_Ml + p*8192 + ofs) = l;
        }
    }
}

// ---------------------------------------------------------------------------
// Stage 1 (v5 — proven 103.1us config): Bu = x @ B^T. 64-row tiles, grid 512,
// 256 threads, 3 CTA/SM (smem 64 KB, regs capped 85). x staged RAW via
// cp.async; split from smem; B double-buffered. raw(kc+1)+B(kc+1) issued
// after the post-split barrier, overlapping MMA(kc). Race-free.
// ---------------------------------------------------------------------------
#define B1_RAW   0                           // 16 KB raw f32 x chunk
#define B1_XHI   16384                       // 8 KB split hi
#define B1_XLO   24576                       // 8 KB split lo
#define B1_BHI(b) (32768 + (b)*16384)        // B chunk hi
#define B1_BLO(b) (40960 + (b)*16384)        // B chunk lo
#define B1_SMEM  65536

__global__ __launch_bounds__(256, 3) void bu_mma(const float* __restrict__ x) {
    extern __shared__ char sm[];
    uint32_t smb = smem_u32(sm);
    int tid = threadIdx.x, wid = tid >> 5, lane = tid & 31;
    int row0 = blockIdx.x * 64;
    int mrow = (wid >> 2) * 32, ncol = (wid & 3) * 16;

    float acc[2][2][4];
    #pragma unroll
    for (int mf = 0; mf < 2; mf++)
        #pragma unroll
        for (int nf = 0; nf < 2; nf++)
            #pragma unroll
            for (int cc = 0; cc < 4; cc++) acc[mf][nf][cc] = 0.f;

    int a_r = lane & 15, a_k = (lane >> 4) << 4;
    int b_m = lane >> 3;
    int b_n = ((b_m >> 1) << 3) + (lane & 7);
    int b_k = (b_m & 1) << 4;

    // prologue: request raw x(0) + B(0)
    #pragma unroll
    for (int it = 0; it < 4; it++) {
        int f = it*256 + tid;                 // 0..1023 (16B lines)
        int r = f >> 4, c4 = (f & 15) << 2;
        cpa16(smb + B1_RAW + f*16, &x[(size_t)(row0 + r)*DM + c4]);
    }
    #pragma unroll
    for (int it = 0; it < 4; it++) {
        int f = it*256 + tid;
        int buf = f >> 9, idx = f & 511;
        cpa16(smb + (buf ? B1_BLO(0) : B1_BHI(0)) + idx*16,
              (buf ? g_Bl : g_Bh) + idx*16);
    }
    CPA_COMMIT();

    #pragma unroll
    for (int kc = 0; kc < 8; kc++) {
        int cur = kc & 1, nxt = cur ^ 1;
        CPA_WAIT(0);       // raw(kc) + B(kc) landed
        __syncthreads();   // + all MMA(kc-1) reads (incl. B(nxt)) complete
        // split raw f32 -> XHI/XLO bf16
        #pragma unroll
        for (int it = 0; it < 4; it++) {
            int f = it*256 + tid;
            int r = f >> 4, c4 = (f & 15) << 2;
            float4 v = *(const float4*)(sm + B1_RAW + f*16);
            uint32_t h0, l0, h1, l1;
            split_pair(v.x, v.y, h0, l0);
            split_pair(v.z, v.w, h1, l1);
            uint32_t off = SW((uint32_t)(r*128 + c4*2));
            *(uint2*)(sm + B1_XHI + off) = make_uint2(h0, h1);
            *(uint2*)(sm + B1_XLO + off) = make_uint2(l0, l1);
        }
        __syncthreads();   // split visible; RAW free for rewrite
        if (kc < 7) {
            // prefetch chunk kc+1 (overlaps MMA(kc))
            #pragma unroll
            for (int it = 0; it < 4; it++) {
                int f = it*256 + tid;
                int r = f >> 4, c4 = (f & 15) << 2;
                cpa16(smb + B1_RAW + f*16,
                      &x[(size_t)(row0 + r)*DM + (kc + 1)*64 + c4]);
            }
            #pragma unroll
            for (int it = 0; it < 4; it++) {
                int f = it*256 + tid;
                int buf = f >> 9, idx = f & 511;
                cpa16(smb + (buf ? B1_BLO(nxt) : B1_BHI(nxt)) + idx*16,
                      (buf ? g_Bl : g_Bh) + (kc + 1)*8192 + idx*16);
            }
            CPA_COMMIT();
        }
        #pragma unroll
        for (int ks = 0; ks < 4; ks++) {
            uint32_t ah[2][4], al[2][4];
            #pragma unroll
            for (int mf = 0; mf < 2; mf++) {
                uint32_t off = SW((uint32_t)((mrow + mf*16 + a_r)*128 + ks*32 + a_k));
                ldsm4(ah[mf], smb + B1_XHI + off);
                ldsm4(al[mf], smb + B1_XLO + off);
            }
            uint32_t boff = SW((uint32_t)((ncol + b_n)*128 + ks*32 + b_k));
            uint32_t bh[4], bl[4];
            ldsm4(bh, smb + B1_BHI(cur) + boff);
            ldsm4(bl, smb + B1_BLO(cur) + boff);
            #pragma unroll
            for (int mf = 0; mf < 2; mf++) {
                mma_bf16(acc[mf][0], ah[mf], bh[0], bh[1]);
                mma_bf16(acc[mf][0], ah[mf], bl[0], bl[1]);
                mma_bf16(acc[mf][0], al[mf], bh[0], bh[1]);
                mma_bf16(acc[mf][1], ah[mf], bh[2], bh[3]);
                mma_bf16(acc[mf][1], ah[mf], bl[2], bl[3]);
                mma_bf16(acc[mf][1], al[mf], bh[2], bh[3]);
            }
        }
    }
    // spill pre-split + swizzled
    int rg = lane >> 2, q = lane & 3;
    #pragma unroll
    for (int mf = 0; mf < 2; mf++)
        #pragma unroll
        for (int nf = 0; nf < 2; nf++) {
            uint32_t r = (uint32_t)(row0 + mrow + mf*16 + rg);
            uint32_t colb = (uint32_t)(ncol + nf*8 + q*2) * 2;
            uint32_t h, l;
            split_pair(acc[mf][nf][0], acc[mf][nf][1], h, l);
            uint32_t ofs = SW(r*128 + colb);
            *(uint32_t*)(g_Buh + ofs) = h;
            *(uint32_t*)(g_Bul + ofs) = l;
            split_pair(acc[mf][nf][2], acc[mf][nf][3], h, l);
            ofs = SW((r + 8)*128 + colb);
            *(uint32_t*)(g_Buh + ofs) = h;
            *(uint32_t*)(g_Bul + ofs) = l;
        }
}

// ---------------------------------------------------------------------------
// Stage 2: three chained shift-GEMM passes (delta 1,2,4), acc in registers.
// (unchanged — proven ~19us)
// ---------------------------------------------------------------------------
#define P_AHI 0
#define P_ALO 19456
#define P_MHI 38912
#define P_MLO 63488
#define P_SMEM 88064

__global__ __launch_bounds__(288, 2) void pass_mma() {
    extern __shared__ char sm[];
    uint32_t smb = smem_u32(sm);
    int tid = threadIdx.x, wid = tid >> 5, lane = tid & 31;
    int b = blockIdx.x >> 5, c = blockIdx.x & 31;
    int t0 = c * 128;
    size_t gbase = (size_t)b * LSEQ;

    for (int f = tid; f < 256; f += 288) {
        int buf = f >> 7, g = f & 127, pr = g >> 3, j = g & 7;
        int row = (pr < 8) ? pr : pr + 136;
        *(uint4*)(sm + (buf ? P_ALO : P_AHI) + row*128 + j*16) = make_uint4(0,0,0,0);
    }
    for (int f = tid; f < 2176; f += 288) {
        int buf = (f >= 1088) ? 1 : 0;
        int g = buf ? f - 1088 : f;
        int r = g >> 3, j = g & 7;
        int t = t0 - 8 + r;
        size_t ts = (t < 0) ? 0 : (size_t)t;
        cpa16z(smb + (buf ? P_ALO : P_AHI) + (8 + r)*128 + j*16,
               (buf ? g_Bul : g_Buh) + (gbase + ts)*128 + j*16, t >= 0);
    }
    for (int f = tid; f < 3072; f += 288) {
        int buf = (f >= 1536) ? 1 : 0;
        int idx = buf ? f - 1536 : f;
        cpa16(smb + (buf ? P_MLO : P_MHI) + idx*16, (buf ? g_Ml : g_Mh) + idx*16);
    }
    CPA_COMMIT();
    CPA_WAIT(0);
    __syncthreads();

    int i0 = 8 + wid*16;
    int rg = lane >> 2, q = lane & 3;
    int r0 = i0 + rg, r1 = r0 + 8;
    int a_r = lane & 15, a_k = (lane >> 4) << 4;
    int b_m = lane >> 3;
    int b_n = ((b_m >> 1) << 3) + (lane & 7);
    int b_k = (b_m & 1) << 4;

    float acc[8][4];
    #pragma unroll
    for (int nf = 0; nf < 8; nf++) {
        uint32_t colb = (uint32_t)(nf*8 + q*2) * 2;
        uint32_t o0 = SW((uint32_t)(r0*128) + colb);
        uint32_t o1 = SW((uint32_t)(r1*128) + colb);
        float2 h0 = __bfloat1622float2(*(__nv_bfloat162*)(sm + P_AHI + o0));
        float2 l0 = __bfloat1622float2(*(__nv_bfloat162*)(sm + P_ALO + o0));
        float2 h1 = __bfloat1622float2(*(__nv_bfloat162*)(sm + P_AHI + o1));
        float2 l1 = __bfloat1622float2(*(__nv_bfloat162*)(sm + P_ALO + o1));
        acc[nf][0] = h0.x + l0.x; acc[nf][1] = h0.y + l0.y;
        acc[nf][2] = h1.x + l1.x; acc[nf][3] = h1.y + l1.y;
    }

    #pragma unroll
    for (int p = 0; p < 3; p++) {
        const int delta = 1 << p;
        #pragma unroll
        for (int ks = 0; ks < 4; ks++) {
            uint32_t ah[4], al[4];
            uint32_t aoff = SW((uint32_t)((i0 - delta + a_r)*128 + ks*32 + a_k));
            ldsm4(ah, smb + P_AHI + aoff);
            ldsm4(al, smb + P_ALO + aoff);
            #pragma unroll
            for (int nfp = 0; nfp < 4; nfp++) {
                uint32_t boff = p*8192 + SW((uint32_t)((nfp*16 + b_n)*128 + ks*32 + b_k));
                uint32_t bh[4], bl[4];
                ldsm4(bh, smb + P_MHI + boff);
                ldsm4(bl, smb + P_MLO + boff);
                mma_bf16(acc[2*nfp],   ah, bh[0], bh[1]);
                mma_bf16(acc[2*nfp],   ah, bl[0], bl[1]);
                mma_bf16(acc[2*nfp],   al, bh[0], bh[1]);
                mma_bf16(acc[2*nfp+1], ah, bh[2], bh[3]);
                mma_bf16(acc[2*nfp+1], ah, bl[2], bl[3]);
                mma_bf16(acc[2*nfp+1], al, bh[2], bh[3]);
            }
        }
        if (p < 2) {
            __syncthreads();
            #pragma unroll
            for (int nf = 0; nf < 8; nf++) {
                uint32_t colb = (uint32_t)(nf*8 + q*2) * 2;
                uint32_t h, l;
                split_pair(acc[nf][0], acc[nf][1], h, l);
                uint32_t off = SW((uint32_t)(r0*128) + colb);
                *(uint32_t*)(sm + P_AHI + off) = h;
                *(uint32_t*)(sm + P_ALO + off) = l;
                split_pair(acc[nf][2], acc[nf][3], h, l);
                off = SW((uint32_t)(r1*128) + colb);
                *(uint32_t*)(sm + P_AHI + off) = h;
                *(uint32_t*)(sm + P_ALO + off) = l;
            }
            __syncthreads();
        }
    }
    if (r0 >= 16 && r0 < 144) {
        uint32_t R = (uint32_t)(gbase + t0 + r0 - 16);
        #pragma unroll
        for (int nf = 0; nf < 8; nf++) {
            uint32_t colb = (uint32_t)(nf*8 + q*2) * 2;
            uint32_t h, l;
            split_pair(acc[nf][0], acc[nf][1], h, l);
            uint32_t ofs = SW(R*128 + colb);
            *(uint32_t*)(g_Sth + ofs) = h;
            *(uint32_t*)(g_Stl + ofs) = l;
        }
    }
    if (r1 >= 16 && r1 < 144) {
        uint32_t R = (uint32_t)(gbase + t0 + r1 - 16);
        #pragma unroll
        for (int nf = 0; nf < 8; nf++) {
            uint32_t colb = (uint32_t)(nf*8 + q*2) * 2;
            uint32_t h, l;
            split_pair(acc[nf][2], acc[nf][3], h, l);
            uint32_t ofs = SW(R*128 + colb);
            *(uint32_t*)(g_Sth + ofs) = h;
            *(uint32_t*)(g_Stl + ofs) = l;
        }
    }
}

// ---------------------------------------------------------------------------
// Stage 3 (persistent — proven R12 config): grid=128, 512 threads, C staged
// ONCE; 4 row-tiles of 64 rows each, S double-buffered. Warp grid 2M x 8N.
// GELU poly + LayerNorm(512). RF/LDS-chain bound at 16 warps/SM (R15 showed
// 32 warps regresses).
// ---------------------------------------------------------------------------
#define O_CHI 0
#define O_CLO 65536
#define O_SHI(b) (131072 + (b)*8192)
#define O_SLO(b) (147456 + (b)*8192)
#define O_GM   163840
#define O_BT   165888
#define O_PART 167936
#define O_SMEM 172032
#define O_GRID 128
#define O_ITERS (NROWS/64/O_GRID)

__global__ __launch_bounds__(512) void out_mma(const float* __restrict__ gamma,
                                               const float* __restrict__ beta,
                                               float* __restrict__ out) {
    extern __shared__ char sm[];
    uint32_t smb = smem_u32(sm);
    int tid = threadIdx.x, wid = tid >> 5, lane = tid & 31;
    int mg = wid >> 3, colw = wid & 7;

    #pragma unroll
    for (int it = 0; it < 16; it++) {
        int f = it*512 + tid;
        int buf = f >> 12, g = f & 4095;
        cpa16(smb + (buf ? O_CLO : O_CHI) + g*16, (buf ? g_Cl : g_Ch) + g*16);
    }
    {
        size_t row0 = (size_t)blockIdx.x * 64;
        #pragma unroll
        for (int it = 0; it < 2; it++) {
            int f = it*512 + tid;
            int buf = f >> 9, g = f & 511, r = g >> 3, j = g & 7;
            cpa16(smb + (buf ? O_SLO(0) : O_SHI(0)) + r*128 + j*16,
                  (buf ? g_Stl : g_Sth) + (row0 + r)*128 + j*16);
        }
    }
    CPA_COMMIT();
    ((float*)(sm + O_GM))[tid] = gamma[tid];
    ((float*)(sm + O_BT))[tid] = beta[tid];

    int a_r = lane & 15, a_k = (lane >> 4) << 4;
    int b_m = lane >> 3;
    int b_n = ((b_m >> 1) << 3) + (lane & 7);
    int b_k = (b_m & 1) << 4;
    int rg = lane >> 2, q = lane & 3;
    const float* gm = (const float*)(sm + O_GM);
    const float* bt = (const float*)(sm + O_BT);
    float2* part = (float2*)(sm + O_PART);

    for (int it = 0; it < O_ITERS; it++) {
        int cur = it & 1;
        int tile = blockIdx.x + it*O_GRID;
        int row0 = tile * 64;

        CPA_WAIT(0);
        __syncthreads();

        if (it < O_ITERS - 1) {
            size_t nrow0 = (size_t)(blockIdx.x + (it + 1)*O_GRID) * 64;
            #pragma unroll
            for (int jt = 0; jt < 2; jt++) {
                int f = jt*512 + tid;
                int buf = f >> 9, g = f & 511, r = g >> 3, j = g & 7;
                cpa16(smb + (buf ? O_SLO(cur^1) : O_SHI(cur^1)) + r*128 + j*16,
                      (buf ? g_Stl : g_Sth) + (nrow0 + r)*128 + j*16);
            }
            CPA_COMMIT();
        }

        float acc[2][8][4];
        #pragma unroll
        for (int mf = 0; mf < 2; mf++)
            #pragma unroll
            for (int nf = 0; nf < 8; nf++)
                #pragma unroll
                for (int cc = 0; cc < 4; cc++) acc[mf][nf][cc] = 0.f;

        #pragma unroll
        for (int ks = 0; ks < 4; ks++) {
            uint32_t ah[2][4], al[2][4];
            #pragma unroll
            for (int mf = 0; mf < 2; mf++) {
                uint32_t aoff = SW((uint32_t)((mg*32 + mf*16 + a_r)*128 + ks*32 + a_k));
                ldsm4(ah[mf], smb + O_SHI(cur) + aoff);
                ldsm4(al[mf], smb + O_SLO(cur) + aoff);
            }
            #pragma unroll
            for (int nfp = 0; nfp < 4; nfp++) {
                uint32_t boff = SW((uint32_t)((colw*64 + nfp*16 + b_n)*128 + ks*32 + b_k));
                uint32_t bh[4], bl[4];
                ldsm4(bh, smb + O_CHI + boff);
                ldsm4(bl, smb + O_CLO + boff);
                #pragma unroll
                for (int mf = 0; mf < 2; mf++) {
                    mma_bf16(acc[mf][2*nfp],   ah[mf], bh[0], bh[1]);
                    mma_bf16(acc[mf][2*nfp],   ah[mf], bl[0], bl[1]);
                    mma_bf16(acc[mf][2*nfp],   al[mf], bh[0], bh[1]);
                    mma_bf16(acc[mf][2*nfp+1], ah[mf], bh[2], bh[3]);
                    mma_bf16(acc[mf][2*nfp+1], ah[mf], bl[2], bl[3]);
                    mma_bf16(acc[mf][2*nfp+1], al[mf], bh[2], bh[3]);
                }
            }
        }
        // ---- epilogue: GELU (warp-uniform poly/exact) + LayerNorm ----
        float am = 0.f;
        #pragma unroll
        for (int mf = 0; mf < 2; mf++)
            #pragma unroll
            for (int nf = 0; nf < 8; nf++)
                #pragma unroll
                for (int cc = 0; cc < 4; cc++) am = fmaxf(am, fabsf(acc[mf][nf][cc]));
        if (__any_sync(0xffffffffu, am > 0.70f)) {
            #pragma unroll
            for (int mf = 0; mf < 2; mf++)
                #pragma unroll
                for (int nf = 0; nf < 8; nf++)
                    #pragma unroll
                    for (int cc = 0; cc < 4; cc++)
                        acc[mf][nf][cc] = gelu_exact(acc[mf][nf][cc]);
        } else {
            #pragma unroll
            for (int mf = 0; mf < 2; mf++)
                #pragma unroll
                for (int nf = 0; nf < 8; nf++)
                    #pragma unroll
                    for (int cc = 0; cc < 4; cc++)
                        acc[mf][nf][cc] = gelu_poly(acc[mf][nf][cc]);
        }
        float s[2][2] = {{0.f,0.f},{0.f,0.f}}, qs[2][2] = {{0.f,0.f},{0.f,0.f}};
        #pragma unroll
        for (int mf = 0; mf < 2; mf++)
            #pragma unroll
            for (int nf = 0; nf < 8; nf++) {
                s[mf][0]  += acc[mf][nf][0] + acc[mf][nf][1];
                qs[mf][0] += acc[mf][nf][0]*acc[mf][nf][0] + acc[mf][nf][1]*acc[mf][nf][1];
                s[mf][1]  += acc[mf][nf][2] + acc[mf][nf][3];
                qs[mf][1] += acc[mf][nf][2]*acc[mf][nf][2] + acc[mf][nf][3]*acc[mf][nf][3];
            }
        #pragma unroll
        for (int off = 1; off <= 2; off <<= 1)
            #pragma unroll
            for (int mf = 0; mf < 2; mf++)
                #pragma unroll
                for (int rh = 0; rh < 2; rh++) {
                    s[mf][rh]  += __shfl_xor_sync(0xffffffffu, s[mf][rh], off);
                    qs[mf][rh] += __shfl_xor_sync(0xffffffffu, qs[mf][rh], off);
                }
        if (q == 0) {
            #pragma unroll
            for (int mf = 0; mf < 2; mf++)
                #pragma unroll
                for (int rh = 0; rh < 2; rh++) {
                    int lr = mg*32 + mf*16 + rg + rh*8;
                    part[lr*8 + colw] = make_float2(s[mf][rh], qs[mf][rh]);
                }
        }
        __syncthreads();
        float mean[2][2], rstd[2][2];
        #pragma unroll
        for (int mf = 0; mf < 2; mf++)
            #pragma unroll
            for (int rh = 0; rh < 2; rh++) {
                int lr = mg*32 + mf*16 + rg + rh*8;
                float ts = 0.f, tq = 0.f;
                #pragma unroll
                for (int cw = 0; cw < 8; cw++) {
                    float2 v = part[lr*8 + cw];
                    ts += v.x; tq += v.y;
                }
                float m = ts * (1.0f/512.0f);
                mean[mf][rh] = m;
                rstd[mf][rh] = rsqrtf(tq * (1.0f/512.0f) - m*m + 1e-5f);
            }
        #pragma unroll
        for (int mf = 0; mf < 2; mf++)
            #pragma unroll
            for (int nf = 0; nf < 8; nf++) {
                int nfp = nf >> 1, h = nf & 1;
                int col = colw*64 + nfp*16 + h*8 + q*2;
                size_t r0g = (size_t)(row0 + mg*32 + mf*16 + rg);
                float2 o0 = make_float2(
                    (acc[mf][nf][0] - mean[mf][0])*rstd[mf][0]*gm[col]   + bt[col],
                    (acc[mf][nf][1] - mean[mf][0])*rstd[mf][0]*gm[col+1] + bt[col+1]);
                float2 o1 = make_float2(
                    (acc[mf][nf][2] - mean[mf][1])*rstd[mf][1]*gm[col]   + bt[col],
                    (acc[mf][nf][3] - mean[mf][1])*rstd[mf][1]*gm[col+1] + bt[col+1]);
                *(float2*)&out[r0g*DM + col] = o0;
                *(float2*)&out[(r0g + 8)*DM + col] = o1;
            }
    }
}

// ---------------------------------------------------------------------------
extern "C" void kernel_launch(void* const* d_in, const int* in_sizes, int n_in,
                              void* d_out, int out_size) {
    const float* x     = (const float*)d_in[0];
    const float* A     = (const float*)d_in[1];
    const float* B     = (const float*)d_in[2];
    const float* C     = (const float*)d_in[3];
    const float* gamma = (const float*)d_in[4];
    const float* beta  = (const float*)d_in[5];
    float* out = (float*)d_out;

    cudaFuncSetAttribute(bu_mma,   cudaFuncAttributeMaxDynamicSharedMemorySize, B1_SMEM);
    cudaFuncSetAttribute(pass_mma, cudaFuncAttributeMaxDynamicSharedMemorySize, P_SMEM);
    cudaFuncSetAttribute(out_mma,  cudaFuncAttributeMaxDynamicSharedMemorySize, O_SMEM);

    init_kernel<<<129, 512>>>(A, B, C);
    bu_mma<<<NROWS/64, 256, B1_SMEM>>>(x);
    pass_mma<<<BSZ * (LSEQ/128), 288, P_SMEM>>>();
    out_mma<<<O_GRID, 512, O_SMEM>>>(gamma, beta, out);
}